// round 1
// baseline (speedup 1.0000x reference)
#include <cuda_runtime.h>
#include <cstdint>

#define N_NODES 100000
#define N_EDGES 1600000
#define D 32            // D_IN == D_OUT == 32

// Scratch (allocation-free): neighbor sums + degrees, zeroed each launch.
__device__ float4 g_nsum[N_NODES * (D / 4)];
__device__ float  g_deg[N_NODES];

// ---------------------------------------------------------------------------
// Pass 1: zero the accumulators
// ---------------------------------------------------------------------------
__global__ void zero_kernel() {
    int i = blockIdx.x * blockDim.x + threadIdx.x;
    int total4 = N_NODES * (D / 4);
    for (int k = i; k < total4; k += gridDim.x * blockDim.x) {
        g_nsum[k] = make_float4(0.f, 0.f, 0.f, 0.f);
    }
    for (int k = i; k < N_NODES; k += gridDim.x * blockDim.x) {
        g_deg[k] = 0.f;
    }
}

// ---------------------------------------------------------------------------
// Pass 2: edge-parallel gather + vector reduction scatter
// One thread per edge: 8x LDG.128 (MLP=8) + 8x red.global.add.v4.f32 + 1 deg red
// ---------------------------------------------------------------------------
__device__ __forceinline__ void red_add_v4(float4* addr, float4 v) {
    asm volatile("red.global.add.v4.f32 [%0], {%1, %2, %3, %4};"
                 :: "l"(addr), "f"(v.x), "f"(v.y), "f"(v.z), "f"(v.w)
                 : "memory");
}
__device__ __forceinline__ void red_add_f32(float* addr, float v) {
    asm volatile("red.global.add.f32 [%0], %1;"
                 :: "l"(addr), "f"(v) : "memory");
}

__global__ void __launch_bounds__(256) edge_kernel(
    const float4* __restrict__ feat4,   // [N_NODES][8]
    const int* __restrict__ src,
    const int* __restrict__ dst)
{
    int e = blockIdx.x * blockDim.x + threadIdx.x;
    if (e >= N_EDGES) return;
    int s = src[e];
    int d = dst[e];
    const float4* fs = feat4 + (size_t)s * (D / 4);
    float4* nd = g_nsum + (size_t)d * (D / 4);

    // Load full source row first (8 independent LDG.128 -> high MLP)
    float4 v[8];
#pragma unroll
    for (int j = 0; j < 8; ++j) v[j] = fs[j];
#pragma unroll
    for (int j = 0; j < 8; ++j) red_add_v4(nd + j, v[j]);

    red_add_f32(&g_deg[d], 1.0f);
}

// ---------------------------------------------------------------------------
// Pass 3: per-node combine. One warp per node (grid-stride). Lane = output
// column; weight columns live in registers; input rows broadcast via shfl.
// out[n][o] = b[o] + sum_i feat[n][i]*Ws[o][i] + (nsum[n][i]/max(deg,1))*Wn[o][i]
// ---------------------------------------------------------------------------
__global__ void __launch_bounds__(256) combine_kernel(
    const float* __restrict__ feat,
    const float* __restrict__ W_self,   // [D_OUT][D_IN] row-major
    const float* __restrict__ W_neigh,
    const float* __restrict__ b_neigh,
    float* __restrict__ out)
{
    const int lane = threadIdx.x & 31;
    const int warp_global = (blockIdx.x * blockDim.x + threadIdx.x) >> 5;
    const int n_warps = (gridDim.x * blockDim.x) >> 5;

    // Each lane owns output column `lane`: cache W rows in registers.
    float ws[D], wn[D];
#pragma unroll
    for (int i = 0; i < D; ++i) {
        ws[i] = W_self[lane * D + i];
        wn[i] = W_neigh[lane * D + i];
    }
    const float bias = b_neigh[lane];
    const float* nsum = reinterpret_cast<const float*>(g_nsum);

    for (int n = warp_global; n < N_NODES; n += n_warps) {
        float f  = feat[n * D + lane];
        float dg = g_deg[n];
        float inv = 1.0f / fmaxf(dg, 1.0f);
        float nb = nsum[n * D + lane] * inv;

        float acc = bias;
#pragma unroll
        for (int i = 0; i < D; ++i) {
            acc += __shfl_sync(0xffffffffu, f,  i) * ws[i];
            acc += __shfl_sync(0xffffffffu, nb, i) * wn[i];
        }
        out[n * D + lane] = acc;
    }
}

// ---------------------------------------------------------------------------
// Launch
// inputs (metadata order): feat, W_self, W_neigh, b_neigh, src, dst
// ---------------------------------------------------------------------------
extern "C" void kernel_launch(void* const* d_in, const int* in_sizes, int n_in,
                              void* d_out, int out_size)
{
    const float* feat    = (const float*)d_in[0];
    const float* W_self  = (const float*)d_in[1];
    const float* W_neigh = (const float*)d_in[2];
    const float* b_neigh = (const float*)d_in[3];
    const int*   src     = (const int*)d_in[4];
    const int*   dst     = (const int*)d_in[5];
    float* out = (float*)d_out;

    zero_kernel<<<592, 256>>>();

    edge_kernel<<<(N_EDGES + 255) / 256, 256>>>(
        (const float4*)feat, src, dst);

    combine_kernel<<<1184, 256>>>(feat, W_self, W_neigh, b_neigh, out);
}

// round 2
// speedup vs baseline: 1.2116x; 1.2116x over previous
#include <cuda_runtime.h>
#include <cstdint>

#define N_NODES 100000
#define N_EDGES 1600000
#define D 32
#define SCAN_BLK 1024
#define N_SCAN_BLOCKS ((N_NODES + SCAN_BLK - 1) / SCAN_BLK)   // 98

// Allocation-free scratch
__device__ int g_cnt[N_NODES];        // per-dst count (== degree)
__device__ int g_offs[N_NODES];       // exclusive scan of cnt
__device__ int g_bsum[N_SCAN_BLOCKS]; // per-scan-block totals
__device__ int g_bscan[N_SCAN_BLOCKS];
__device__ int g_pos[N_EDGES];        // rank of edge within its dst segment
__device__ int g_sorted[N_EDGES];     // src ids grouped by dst

// ---------------------------------------------------------------------------
__global__ void zero_cnt() {
    int i = blockIdx.x * blockDim.x + threadIdx.x;
    if (i < N_NODES) g_cnt[i] = 0;
}

// Pass A: per-dst counters + per-edge rank
__global__ void __launch_bounds__(256) pass_rank(const int* __restrict__ dst) {
    int e = blockIdx.x * blockDim.x + threadIdx.x;
    if (e >= N_EDGES) return;
    g_pos[e] = atomicAdd(&g_cnt[dst[e]], 1);
}

// Scan stage 1: block-local exclusive scan (Kogge-Stone in smem)
__global__ void __launch_bounds__(SCAN_BLK) scan1() {
    __shared__ int sh[SCAN_BLK];
    int tid = threadIdx.x;
    int gid = blockIdx.x * SCAN_BLK + tid;
    int v = (gid < N_NODES) ? g_cnt[gid] : 0;
    sh[tid] = v;
    __syncthreads();
#pragma unroll
    for (int off = 1; off < SCAN_BLK; off <<= 1) {
        int t = 0;
        if (tid >= off) t = sh[tid - off];
        __syncthreads();
        if (tid >= off) sh[tid] += t;
        __syncthreads();
    }
    if (gid < N_NODES) g_offs[gid] = sh[tid] - v;   // exclusive
    if (tid == SCAN_BLK - 1) g_bsum[blockIdx.x] = sh[tid];
}

// Scan stage 2: exclusive scan of block sums (single block)
__global__ void scan2() {
    __shared__ int sh[128];
    int tid = threadIdx.x;
    int v = (tid < N_SCAN_BLOCKS) ? g_bsum[tid] : 0;
    sh[tid] = v;
    __syncthreads();
#pragma unroll
    for (int off = 1; off < 128; off <<= 1) {
        int t = 0;
        if (tid >= off) t = sh[tid - off];
        __syncthreads();
        if (tid >= off) sh[tid] += t;
        __syncthreads();
    }
    if (tid < N_SCAN_BLOCKS) g_bscan[tid] = sh[tid] - v;
}

// Scan stage 3: add block offsets
__global__ void __launch_bounds__(SCAN_BLK) scan3() {
    int gid = blockIdx.x * SCAN_BLK + threadIdx.x;
    if (gid < N_NODES) g_offs[gid] += g_bscan[blockIdx.x];
}

// Pass B: scatter src ids into dst-grouped order (no atomics)
__global__ void __launch_bounds__(256) pass_scatter(const int* __restrict__ src,
                                                    const int* __restrict__ dst) {
    int e = blockIdx.x * blockDim.x + threadIdx.x;
    if (e >= N_EDGES) return;
    g_sorted[g_offs[dst[e]] + g_pos[e]] = src[e];
}

// Pass C: fused segment-mean + GraphSAGE combine. One warp per dst node.
__global__ void __launch_bounds__(256) aggregate_combine(
    const float* __restrict__ feat,
    const float* __restrict__ W_self,
    const float* __restrict__ W_neigh,
    const float* __restrict__ b_neigh,
    float* __restrict__ out)
{
    const int lane = threadIdx.x & 31;
    const int warp = (blockIdx.x * blockDim.x + threadIdx.x) >> 5;
    const int n_warps = (gridDim.x * blockDim.x) >> 5;

    // lane owns output column `lane`; weight rows in registers
    float ws[D], wn[D];
#pragma unroll
    for (int i = 0; i < D; ++i) {
        ws[i] = W_self[lane * D + i];
        wn[i] = W_neigh[lane * D + i];
    }
    const float bias = b_neigh[lane];

    for (int n = warp; n < N_NODES; n += n_warps) {
        const int start = g_offs[n];
        const int cnt   = g_cnt[n];

        float acc = 0.f;
        for (int base = 0; base < cnt; base += 32) {
            int rem = cnt - base;
            int m = rem < 32 ? rem : 32;
            int sv = (lane < m) ? g_sorted[start + base + lane] : 0;
            int i = 0;
            for (; i + 4 <= m; i += 4) {
                int s0 = __shfl_sync(0xffffffffu, sv, i);
                int s1 = __shfl_sync(0xffffffffu, sv, i + 1);
                int s2 = __shfl_sync(0xffffffffu, sv, i + 2);
                int s3 = __shfl_sync(0xffffffffu, sv, i + 3);
                float a0 = feat[s0 * D + lane];
                float a1 = feat[s1 * D + lane];
                float a2 = feat[s2 * D + lane];
                float a3 = feat[s3 * D + lane];
                acc += a0; acc += a1; acc += a2; acc += a3;
            }
            for (; i < m; ++i) {
                int s = __shfl_sync(0xffffffffu, sv, i);
                acc += feat[s * D + lane];
            }
        }

        const float inv = 1.0f / fmaxf((float)cnt, 1.0f);
        const float nb = acc * inv;
        const float f  = feat[n * D + lane];

        float o = bias;
#pragma unroll
        for (int i = 0; i < D; ++i) {
            o += __shfl_sync(0xffffffffu, f,  i) * ws[i];
            o += __shfl_sync(0xffffffffu, nb, i) * wn[i];
        }
        out[n * D + lane] = o;
    }
}

// ---------------------------------------------------------------------------
// inputs: feat, W_self, W_neigh, b_neigh, src, dst
extern "C" void kernel_launch(void* const* d_in, const int* in_sizes, int n_in,
                              void* d_out, int out_size)
{
    const float* feat    = (const float*)d_in[0];
    const float* W_self  = (const float*)d_in[1];
    const float* W_neigh = (const float*)d_in[2];
    const float* b_neigh = (const float*)d_in[3];
    const int*   src     = (const int*)d_in[4];
    const int*   dst     = (const int*)d_in[5];
    float* out = (float*)d_out;

    zero_cnt<<<(N_NODES + 255) / 256, 256>>>();
    pass_rank<<<(N_EDGES + 255) / 256, 256>>>(dst);
    scan1<<<N_SCAN_BLOCKS, SCAN_BLK>>>();
    scan2<<<1, 128>>>();
    scan3<<<N_SCAN_BLOCKS, SCAN_BLK>>>();
    pass_scatter<<<(N_EDGES + 255) / 256, 256>>>(src, dst);
    aggregate_combine<<<1184, 256>>>(feat, W_self, W_neigh, b_neigh, out);
}